// round 7
// baseline (speedup 1.0000x reference)
#include <cuda_runtime.h>
#include <cstdint>
#include <cstddef>

#define TPB   512
#define NKEY  127
#define NH    4
#define DK    64
#define DOUT  256
#define STR   68   // padded row stride (floats)

static constexpr int KV_FLOATS = 128 * STR;
static constexpr int WK_FLOATS = DOUT * STR;
static constexpr int OFF_KV0  = 0;
static constexpr int OFF_KV1  = OFF_KV0 + KV_FLOATS;
static constexpr int OFF_WK   = OFF_KV1 + KV_FLOATS;
static constexpr int OFF_QB   = OFF_WK + WK_FLOATS;
static constexpr int OFF_Q    = OFF_QB + DOUT;
static constexpr int OFF_WS   = OFF_Q + DK;
static constexpr int OFF_BIAS = OFF_WS + DK;
static constexpr int OFF_SC   = OFF_BIAS + DK;          // [4][128]
static constexpr int OFF_W    = OFF_SC + NH * 128;      // [128][4] n-major
static constexpr int OFF_WV   = OFF_W + 128 * NH;       // [256]
static constexpr int OFF_PART = OFF_WV + DOUT;          // [256][8]
static constexpr int OFF_BS   = OFF_PART + DOUT * 8;
static constexpr int SMEM_FLOATS = OFF_BS + 4;
static constexpr int SMEM_BYTES  = SMEM_FLOATS * 4;

__device__ __forceinline__ float tanh_fast(float x) {
    float y;
    asm("tanh.approx.f32 %0, %1;" : "=f"(y) : "f"(x));
    return y;
}

// m16n8k8 tf32 MMA, row(A) x col(B), fp32 accumulate (arch-neutral PTX)
__device__ __forceinline__ void mma8(float& d0, float& d1, float& d2, float& d3,
                                     float a0, float a1, float a2, float a3,
                                     float b0, float b1) {
    asm volatile(
        "mma.sync.aligned.m16n8k8.row.col.f32.tf32.tf32.f32 "
        "{%0,%1,%2,%3}, {%4,%5,%6,%7}, {%8,%9}, {%0,%1,%2,%3};"
        : "+f"(d0), "+f"(d1), "+f"(d2), "+f"(d3)
        : "r"(__float_as_uint(a0)), "r"(__float_as_uint(a1)),
          "r"(__float_as_uint(a2)), "r"(__float_as_uint(a3)),
          "r"(__float_as_uint(b0)), "r"(__float_as_uint(b1)));
}

#define CP_ASYNC16(sdst, gsrc)                                                \
    asm volatile("cp.async.cg.shared.global [%0], [%1], 16;"                  \
                 :: "r"(sdst), "l"(gsrc))
#define CP_COMMIT() asm volatile("cp.async.commit_group;")
#define CP_WAIT1()  asm volatile("cp.async.wait_group 1;")

__device__ __forceinline__ void prefetch_kv(const float* __restrict__ gsrc,
                                            float* sdst) {
    #pragma unroll 1
    for (int j = threadIdx.x; j < NKEY * 16; j += TPB) {
        int row = j >> 4;
        int c4  = j & 15;
        unsigned sa =
            (unsigned)__cvta_generic_to_shared(sdst + row * STR + c4 * 4);
        CP_ASYNC16(sa, gsrc + j * 4);
    }
}

__global__ void __launch_bounds__(TPB, 1)
raamh_kernel(const float* __restrict__ q_x, const float* __restrict__ kv_x,
             const float* __restrict__ Wk,  const float* __restrict__ Wq,
             const float* __restrict__ Wv,  const float* __restrict__ bias,
             const float* __restrict__ Ws,  const float* __restrict__ bs,
             float* __restrict__ out, int BT)
{
    extern __shared__ float smem[];
    float* s_kv[2] = { smem + OFF_KV0, smem + OFF_KV1 };
    float* s_wk   = smem + OFF_WK;
    float* s_qb   = smem + OFF_QB;
    float* s_q    = smem + OFF_Q;
    float* s_ws   = smem + OFF_WS;
    float* s_bias = smem + OFF_BIAS;
    float* s_sc   = smem + OFF_SC;
    float* s_w    = smem + OFF_W;     // [n][4] heads, n-major
    float* s_wv   = smem + OFF_WV;
    float* s_part = smem + OFF_PART;  // [256][8]
    float* s_bs   = smem + OFF_BS;

    const int tid  = threadIdx.x;
    const int lane = tid & 31;
    const int wrp  = tid >> 5;        // 0..15
    const int g    = lane >> 2;       // fragment row group
    const int tg   = lane & 3;        // fragment col group
    // score GEMM task decomposition: one task per warp
    const int half = wrp >> 3;                 // o-half
    const int head = half * 2 + ((wrp >> 2) & 1);
    const int wm   = wrp & 3;                  // 32-n block
    // split-k ids for projections
    const int po   = tid & 255;       // output index
    const int pk   = tid >> 8;        // k-half (0/1)

    // ---- one-time staging ----
    {
        const float4* wk4 = (const float4*)Wk;
        #pragma unroll 2
        for (int j = tid; j < DOUT * 16; j += TPB) {
            int row = j >> 4, c4 = j & 15;
            float4 v = wk4[j];
            *(float4*)(s_wk + row * STR + c4 * 4) = v;
        }
        if (tid < DK) {
            s_ws[tid]   = Ws[tid];
            s_bias[tid] = bias[tid];
        }
        if (tid == 0) s_bs[0] = bs[0];
        if (tid < 128) {  // zero garbage row 127 of both kv buffers
            s_kv[tid >> 6][127 * STR + (tid & 63)] = 0.f;
        }
    }

    int bt0 = blockIdx.x;
    int buf = 0;
    prefetch_kv(kv_x + (size_t)bt0 * (NKEY * DK), s_kv[0]);
    CP_COMMIT();

    for (int bt = bt0; bt < BT; bt += gridDim.x) {
        if (tid < DK) s_q[tid] = q_x[bt * DK + tid];

        int bt_next = bt + gridDim.x;
        if (bt_next < BT)
            prefetch_kv(kv_x + (size_t)bt_next * (NKEY * DK), s_kv[buf ^ 1]);
        CP_COMMIT();
        CP_WAIT1();
        __syncthreads();

        const float* kvb = s_kv[buf];

        // ---- q projection + bias, split-k over thread halves ----
        {
            const float4* wq4 = (const float4*)(Wq + po * DK + pk * 32);
            const float*  qq  = s_q + pk * 32;
            float a0 = 0.f, a1 = 0.f, a2 = 0.f, a3 = 0.f;
            #pragma unroll
            for (int i = 0; i < 8; i++) {
                float4 w = __ldg(wq4 + i);
                a0 = fmaf(qq[4 * i + 0], w.x, a0);
                a1 = fmaf(qq[4 * i + 1], w.y, a1);
                a2 = fmaf(qq[4 * i + 2], w.z, a2);
                a3 = fmaf(qq[4 * i + 3], w.w, a3);
            }
            s_part[po * 8 + pk] = (a0 + a1) + (a2 + a3);
        }
        __syncthreads();
        if (tid < DOUT)
            s_qb[tid] = s_part[tid * 8] + s_part[tid * 8 + 1] +
                        s_bias[tid & (DK - 1)];
        __syncthreads();

        const float bsv = s_bs[0];

        // ---- score GEMM via tf32 mma.sync: one warp task each ----
        {
            const float* kvp = kvb + (wm * 32) * STR;
            const float* wkp = s_wk + (head * 64) * STR;

            float acc[2][8][4];
            #pragma unroll
            for (int mb = 0; mb < 2; ++mb)
                #pragma unroll
                for (int nb = 0; nb < 8; ++nb)
                    #pragma unroll
                    for (int c = 0; c < 4; ++c) acc[mb][nb][c] = 0.f;

            #pragma unroll
            for (int kb = 0; kb < 8; ++kb) {
                const int k0 = kb * 8;
                float a[2][4];
                #pragma unroll
                for (int mb = 0; mb < 2; ++mb) {
                    const float* ar = kvp + (mb * 16 + g) * STR + k0 + tg;
                    a[mb][0] = ar[0];
                    a[mb][1] = ar[8 * STR];
                    a[mb][2] = ar[4];
                    a[mb][3] = ar[8 * STR + 4];
                }
                float b[8][2];
                #pragma unroll
                for (int nb = 0; nb < 8; ++nb) {
                    const float* br = wkp + (nb * 8 + g) * STR + k0 + tg;
                    b[nb][0] = br[0];
                    b[nb][1] = br[4];
                }
                #pragma unroll
                for (int mb = 0; mb < 2; ++mb)
                    #pragma unroll
                    for (int nb = 0; nb < 8; ++nb)
                        mma8(acc[mb][nb][0], acc[mb][nb][1],
                             acc[mb][nb][2], acc[mb][nb][3],
                             a[mb][0], a[mb][1], a[mb][2], a[mb][3],
                             b[nb][0], b[nb][1]);
            }

            // epilogue: tanh + Ws reduction over the 64 o of this head
            float part[2][2];
            part[0][0] = part[0][1] = part[1][0] = part[1][1] = 0.f;
            #pragma unroll
            for (int nb = 0; nb < 8; ++nb) {
                #pragma unroll
                for (int cc = 0; cc < 2; ++cc) {
                    const int k = nb * 8 + tg * 2 + cc;
                    const float wsk = s_ws[k];
                    const float qbo = s_qb[head * 64 + k];
                    #pragma unroll
                    for (int mb = 0; mb < 2; ++mb) {
                        part[mb][0] = fmaf(
                            wsk, tanh_fast(acc[mb][nb][cc] + qbo),
                            part[mb][0]);
                        part[mb][1] = fmaf(
                            wsk, tanh_fast(acc[mb][nb][2 + cc] + qbo),
                            part[mb][1]);
                    }
                }
            }
            #pragma unroll
            for (int m = 1; m <= 2; m <<= 1) {
                #pragma unroll
                for (int mb = 0; mb < 2; ++mb) {
                    part[mb][0] += __shfl_xor_sync(0xffffffffu, part[mb][0], m);
                    part[mb][1] += __shfl_xor_sync(0xffffffffu, part[mb][1], m);
                }
            }
            if (tg == 0) {
                #pragma unroll
                for (int mb = 0; mb < 2; ++mb) {
                    const int r = wm * 32 + mb * 16 + g;
                    s_sc[head * 128 + r]     = part[mb][0] + bsv;
                    s_sc[head * 128 + r + 8] = part[mb][1] + bsv;
                }
            }
        }
        __syncthreads();

        // ---- softmax per head (one warp per head), n-major s_w ----
        if (tid < NH * 32) {
            int hh = tid >> 5;
            int ln = tid & 31;
            const float* sc = s_sc + hh * 128;
            float v0 = sc[ln];
            float v1 = sc[ln + 32];
            float v2 = sc[ln + 64];
            float v3 = (ln + 96 < NKEY) ? sc[ln + 96] : -1e30f;
            float m = fmaxf(fmaxf(v0, v1), fmaxf(v2, v3));
            #pragma unroll
            for (int o = 16; o > 0; o >>= 1)
                m = fmaxf(m, __shfl_xor_sync(0xffffffffu, m, o));
            float e0 = __expf(v0 - m);
            float e1 = __expf(v1 - m);
            float e2 = __expf(v2 - m);
            float e3 = (ln + 96 < NKEY) ? __expf(v3 - m) : 0.f;
            float s = (e0 + e1) + (e2 + e3);
            #pragma unroll
            for (int o = 16; o > 0; o >>= 1)
                s += __shfl_xor_sync(0xffffffffu, s, o);
            float inv = 1.f / s;
            s_w[ln * 4 + hh]        = e0 * inv;
            s_w[(ln + 32) * 4 + hh] = e1 * inv;
            s_w[(ln + 64) * 4 + hh] = e2 * inv;
            if (ln + 96 < NKEY) s_w[(ln + 96) * 4 + hh] = e3 * inv;
        }
        __syncthreads();

        // ---- weighted kv sum, eighth-split over n ----
        {
            const int q8 = tid >> 6;          // 8 n-groups of 16
            const int i  = tid & 63;
            float a0 = 0.f, a1 = 0.f, a2 = 0.f, a3 = 0.f;
            const int n0 = q8 * 16;
            const int n1 = (q8 == 7) ? NKEY : n0 + 16;
            #pragma unroll 4
            for (int n = n0; n < n1; ++n) {
                float  v  = kvb[n * STR + i];
                float4 w4 = *(const float4*)(s_w + n * 4);
                a0 = fmaf(w4.x, v, a0);
                a1 = fmaf(w4.y, v, a1);
                a2 = fmaf(w4.z, v, a2);
                a3 = fmaf(w4.w, v, a3);
            }
            s_part[(0 * 64 + i) * 8 + q8] = a0;
            s_part[(1 * 64 + i) * 8 + q8] = a1;
            s_part[(2 * 64 + i) * 8 + q8] = a2;
            s_part[(3 * 64 + i) * 8 + q8] = a3;
        }
        __syncthreads();
        if (tid < DOUT) {
            float4 p0 = *(const float4*)(s_part + tid * 8);
            float4 p1 = *(const float4*)(s_part + tid * 8 + 4);
            s_wv[tid] = ((p0.x + p0.y) + (p0.z + p0.w)) +
                        ((p1.x + p1.y) + (p1.z + p1.w));
        }
        __syncthreads();

        // ---- output projection, split-k over thread halves ----
        {
            const float* wvh = s_wv + (po >> 6) * 64 + pk * 32;
            const float4* wv4 = (const float4*)(Wv + po * DK + pk * 32);
            float a0 = 0.f, a1 = 0.f, a2 = 0.f, a3 = 0.f;
            #pragma unroll
            for (int i = 0; i < 8; i++) {
                float4 w = __ldg(wv4 + i);
                a0 = fmaf(wvh[4 * i + 0], w.x, a0);
                a1 = fmaf(wvh[4 * i + 1], w.y, a1);
                a2 = fmaf(wvh[4 * i + 2], w.z, a2);
                a3 = fmaf(wvh[4 * i + 3], w.w, a3);
            }
            s_part[po * 8 + pk] = (a0 + a1) + (a2 + a3);
        }
        __syncthreads();
        if (tid < DOUT)
            out[(size_t)bt * DOUT + tid] =
                s_part[tid * 8] + s_part[tid * 8 + 1];

        buf ^= 1;
    }
}

extern "C" void kernel_launch(void* const* d_in, const int* in_sizes, int n_in,
                              void* d_out, int out_size) {
    (void)n_in; (void)out_size;
    const float* q_x  = (const float*)d_in[0];
    const float* kv_x = (const float*)d_in[1];
    const float* Wk   = (const float*)d_in[2];
    const float* Wq   = (const float*)d_in[3];
    const float* Wv   = (const float*)d_in[4];
    const float* bias = (const float*)d_in[5];
    const float* Ws   = (const float*)d_in[6];
    const float* bs   = (const float*)d_in[7];
    float* out = (float*)d_out;

    const int BT = in_sizes[0] / DK;
    int grid = BT < 152 ? BT : 152;

    cudaFuncSetAttribute(raamh_kernel,
                         cudaFuncAttributeMaxDynamicSharedMemorySize,
                         SMEM_BYTES);
    raamh_kernel<<<grid, TPB, SMEM_BYTES>>>(q_x, kv_x, Wk, Wq, Wv,
                                            bias, Ws, bs, out, BT);
}

// round 8
// speedup vs baseline: 1.1574x; 1.1574x over previous
#include <cuda_runtime.h>
#include <cstdint>
#include <cstddef>

#define TPB   256
#define NKEY  127
#define NH    4
#define DK    64
#define DOUT  256
#define STR   80   // row stride (floats); 80 mod 32 = 16 -> conflict-free LDS.128
#define MAXT  12   // max tiles per block

static constexpr int KV_FLOATS = 128 * STR;            // 10240
static constexpr int WK_FLOATS = DOUT * STR;           // 20480
static constexpr int OFF_KV0  = 0;
static constexpr int OFF_KV1  = OFF_KV0 + KV_FLOATS;
static constexpr int OFF_WK   = OFF_KV1 + KV_FLOATS;
static constexpr int OFF_QBA  = OFF_WK + WK_FLOATS;     // [MAXT][256]
static constexpr int OFF_QT   = OFF_QBA + MAXT * DOUT;  // [MAXT][64]
static constexpr int OFF_WS   = OFF_QT + MAXT * DK;
static constexpr int OFF_SC   = OFF_WS + DK;            // [4][128]
static constexpr int OFF_W    = OFF_SC + NH * 128;      // [128][4] n-major
static constexpr int OFF_WV   = OFF_W + 128 * NH;       // [256]
static constexpr int OFF_PART = OFF_WV + DOUT;          // [256][4]
static constexpr int OFF_BS   = OFF_PART + DOUT * 4;
static constexpr int SMEM_FLOATS = OFF_BS + 4;
static constexpr int SMEM_BYTES  = SMEM_FLOATS * 4;

__device__ __forceinline__ float tanh_fast(float x) {
    float y;
    asm("tanh.approx.f32 %0, %1;" : "=f"(y) : "f"(x));
    return y;
}

// m16n8k8 tf32 MMA, row(A) x col(B), fp32 accumulate (arch-neutral PTX)
__device__ __forceinline__ void mma8(float& d0, float& d1, float& d2, float& d3,
                                     float a0, float a1, float a2, float a3,
                                     float b0, float b1) {
    asm volatile(
        "mma.sync.aligned.m16n8k8.row.col.f32.tf32.tf32.f32 "
        "{%0,%1,%2,%3}, {%4,%5,%6,%7}, {%8,%9}, {%0,%1,%2,%3};"
        : "+f"(d0), "+f"(d1), "+f"(d2), "+f"(d3)
        : "r"(__float_as_uint(a0)), "r"(__float_as_uint(a1)),
          "r"(__float_as_uint(a2)), "r"(__float_as_uint(a3)),
          "r"(__float_as_uint(b0)), "r"(__float_as_uint(b1)));
}

#define CP_ASYNC16(sdst, gsrc)                                                \
    asm volatile("cp.async.cg.shared.global [%0], [%1], 16;"                  \
                 :: "r"(sdst), "l"(gsrc))
#define CP_COMMIT() asm volatile("cp.async.commit_group;")
#define CP_WAIT1()  asm volatile("cp.async.wait_group 1;")

__device__ __forceinline__ void prefetch_kv(const float* __restrict__ gsrc,
                                            float* sdst) {
    #pragma unroll 2
    for (int j = threadIdx.x; j < NKEY * 16; j += TPB) {
        int row = j >> 4;
        int c4  = j & 15;
        unsigned sa =
            (unsigned)__cvta_generic_to_shared(sdst + row * STR + c4 * 4);
        CP_ASYNC16(sa, gsrc + j * 4);
    }
}

__global__ void __launch_bounds__(TPB, 1)
raamh_kernel(const float* __restrict__ q_x, const float* __restrict__ kv_x,
             const float* __restrict__ Wk,  const float* __restrict__ Wq,
             const float* __restrict__ Wv,  const float* __restrict__ bias,
             const float* __restrict__ Ws,  const float* __restrict__ bs,
             float* __restrict__ out, int BT)
{
    extern __shared__ float smem[];
    float* s_kv[2] = { smem + OFF_KV0, smem + OFF_KV1 };
    float* s_wk   = smem + OFF_WK;
    float* s_qba  = smem + OFF_QBA;   // [MAXT][256] q-proj + bias
    float* s_qt   = smem + OFF_QT;    // [MAXT][64]  raw q vectors
    float* s_ws   = smem + OFF_WS;
    float* s_sc   = smem + OFF_SC;
    float* s_w    = smem + OFF_W;     // [n][4] heads, n-major
    float* s_wv   = smem + OFF_WV;
    float* s_part = smem + OFF_PART;
    float* s_bs   = smem + OFF_BS;

    const int tid  = threadIdx.x;
    const int lane = tid & 31;
    const int wrp  = tid >> 5;
    const int g    = lane >> 2;       // fragment row group
    const int tg   = lane & 3;        // fragment col group
    const int h    = tid >> 6;

    const int bt0  = blockIdx.x;
    const int grid = gridDim.x;
    int ntiles = (BT - bt0 + grid - 1) / grid;
    if (ntiles > MAXT) ntiles = MAXT;

    // ---- one-time staging: Wk (stride 80) + q vectors for all tiles ----
    {
        const float4* wk4 = (const float4*)Wk;
        #pragma unroll 4
        for (int j = tid; j < DOUT * 16; j += TPB) {
            int row = j >> 4, c4 = j & 15;
            float4 v = wk4[j];
            *(float4*)(s_wk + row * STR + c4 * 4) = v;
        }
        if (tid < DK) s_ws[tid] = Ws[tid];
        if (tid == 0) s_bs[0] = bs[0];
        if (tid < 128)   // zero garbage row 127 of both kv buffers
            s_kv[tid >> 6][127 * STR + (tid & 63)] = 0.f;
        for (int idx = tid; idx < ntiles * DK; idx += TPB) {
            int t = idx >> 6, k = idx & 63;
            s_qt[t * DK + k] = q_x[(size_t)(bt0 + t * grid) * DK + k];
        }
    }
    __syncthreads();

    // ---- prologue: qb for every tile (thread owns output o = tid) ----
    {
        float4 wq[16];
        const float4* wq4 = (const float4*)(Wq + tid * DK);
        #pragma unroll
        for (int i = 0; i < 16; i++) wq[i] = __ldg(wq4 + i);
        const float bb = __ldg(bias + (tid & (DK - 1)));
        for (int t = 0; t < ntiles; ++t) {
            const float* qq = s_qt + t * DK;
            float a0 = 0.f, a1 = 0.f, a2 = 0.f, a3 = 0.f;
            #pragma unroll
            for (int i = 0; i < 16; i++) {
                a0 = fmaf(qq[4 * i + 0], wq[i].x, a0);
                a1 = fmaf(qq[4 * i + 1], wq[i].y, a1);
                a2 = fmaf(qq[4 * i + 2], wq[i].z, a2);
                a3 = fmaf(qq[4 * i + 3], wq[i].w, a3);
            }
            s_qba[t * DOUT + tid] = (a0 + a1) + (a2 + a3) + bb;
        }
    }

    int buf = 0;
    prefetch_kv(kv_x + (size_t)bt0 * (NKEY * DK), s_kv[0]);
    CP_COMMIT();

    int ti = 0;
    for (int bt = bt0; bt < BT; bt += grid, ++ti) {
        int bt_next = bt + grid;
        if (bt_next < BT)
            prefetch_kv(kv_x + (size_t)bt_next * (NKEY * DK), s_kv[buf ^ 1]);
        CP_COMMIT();
        CP_WAIT1();
        __syncthreads();

        const float* kvb = s_kv[buf];
        const float* qbt = s_qba + ti * DOUT;
        const float  bsv = s_bs[0];

        // ---- score GEMM via tf32 mma.sync; 2 tasks per warp ----
        // k-slot permutation: super-step ks covers logical k16; MMA0 slots
        // (tg,tg+4) -> (4tg,4tg+1), MMA1 -> (4tg+2,4tg+3). One LDS.128/row.
        #pragma unroll 1
        for (int it = 0; it < 2; ++it) {
            const int task = wrp * 2 + it;        // 0..15
            const int half = task >> 3;
            const int head = half * 2 + ((task >> 2) & 1);
            const int wm   = task & 3;
            const float* kvp = kvb + (wm * 32) * STR;
            const float* wkp = s_wk + (head * 64) * STR;

            float acc[2][8][4];
            #pragma unroll
            for (int mb = 0; mb < 2; ++mb)
                #pragma unroll
                for (int nb = 0; nb < 8; ++nb)
                    #pragma unroll
                    for (int c = 0; c < 4; ++c) acc[mb][nb][c] = 0.f;

            #pragma unroll
            for (int ks = 0; ks < 4; ++ks) {
                const int kc = ks * 16 + tg * 4;
                float4 av[2][2];
                #pragma unroll
                for (int mb = 0; mb < 2; ++mb) {
                    const float* ar = kvp + (mb * 16 + g) * STR + kc;
                    av[mb][0] = *(const float4*)ar;
                    av[mb][1] = *(const float4*)(ar + 8 * STR);
                }
                #pragma unroll
                for (int nb = 0; nb < 8; ++nb) {
                    float4 bv =
                        *(const float4*)(wkp + (nb * 8 + g) * STR + kc);
                    #pragma unroll
                    for (int mb = 0; mb < 2; ++mb) {
                        mma8(acc[mb][nb][0], acc[mb][nb][1],
                             acc[mb][nb][2], acc[mb][nb][3],
                             av[mb][0].x, av[mb][1].x,
                             av[mb][0].y, av[mb][1].y,
                             bv.x, bv.y);
                        mma8(acc[mb][nb][0], acc[mb][nb][1],
                             acc[mb][nb][2], acc[mb][nb][3],
                             av[mb][0].z, av[mb][1].z,
                             av[mb][0].w, av[mb][1].w,
                             bv.z, bv.w);
                    }
                }
            }

            // epilogue: tanh + Ws reduction over this head's 64 o
            float part[2][2];
            part[0][0] = part[0][1] = part[1][0] = part[1][1] = 0.f;
            #pragma unroll
            for (int nb = 0; nb < 8; ++nb) {
                #pragma unroll
                for (int cc = 0; cc < 2; ++cc) {
                    const int k = nb * 8 + tg * 2 + cc;
                    const float wsk = s_ws[k];
                    const float qbo = qbt[head * 64 + k];
                    #pragma unroll
                    for (int mb = 0; mb < 2; ++mb) {
                        part[mb][0] = fmaf(
                            wsk, tanh_fast(acc[mb][nb][cc] + qbo),
                            part[mb][0]);
                        part[mb][1] = fmaf(
                            wsk, tanh_fast(acc[mb][nb][2 + cc] + qbo),
                            part[mb][1]);
                    }
                }
            }
            #pragma unroll
            for (int m = 1; m <= 2; m <<= 1) {
                #pragma unroll
                for (int mb = 0; mb < 2; ++mb) {
                    part[mb][0] += __shfl_xor_sync(0xffffffffu, part[mb][0], m);
                    part[mb][1] += __shfl_xor_sync(0xffffffffu, part[mb][1], m);
                }
            }
            if (tg == 0) {
                #pragma unroll
                for (int mb = 0; mb < 2; ++mb) {
                    const int r = wm * 32 + mb * 16 + g;
                    s_sc[head * 128 + r]     = part[mb][0] + bsv;
                    s_sc[head * 128 + r + 8] = part[mb][1] + bsv;
                }
            }
        }
        __syncthreads();

        // ---- softmax per head (one warp per head), n-major s_w ----
        if (tid < NH * 32) {
            int hh = tid >> 5;
            int ln = tid & 31;
            const float* sc = s_sc + hh * 128;
            float v0 = sc[ln];
            float v1 = sc[ln + 32];
            float v2 = sc[ln + 64];
            float v3 = (ln + 96 < NKEY) ? sc[ln + 96] : -1e30f;
            float m = fmaxf(fmaxf(v0, v1), fmaxf(v2, v3));
            #pragma unroll
            for (int o = 16; o > 0; o >>= 1)
                m = fmaxf(m, __shfl_xor_sync(0xffffffffu, m, o));
            float e0 = __expf(v0 - m);
            float e1 = __expf(v1 - m);
            float e2 = __expf(v2 - m);
            float e3 = (ln + 96 < NKEY) ? __expf(v3 - m) : 0.f;
            float s = (e0 + e1) + (e2 + e3);
            #pragma unroll
            for (int o = 16; o > 0; o >>= 1)
                s += __shfl_xor_sync(0xffffffffu, s, o);
            float inv = 1.f / s;
            s_w[ln * 4 + hh]        = e0 * inv;
            s_w[(ln + 32) * 4 + hh] = e1 * inv;
            s_w[(ln + 64) * 4 + hh] = e2 * inv;
            if (ln + 96 < NKEY) s_w[(ln + 96) * 4 + hh] = e3 * inv;
        }
        __syncthreads();

        // ---- weighted kv sum, quarter-split over n ----
        {
            const int q4 = tid >> 6;
            const int i  = tid & 63;
            float a0 = 0.f, a1 = 0.f, a2 = 0.f, a3 = 0.f;
            const int n0 = q4 * 32;
            const int n1 = (q4 == 3) ? NKEY : n0 + 32;
            #pragma unroll 4
            for (int n = n0; n < n1; ++n) {
                float  v  = kvb[n * STR + i];
                float4 w4 = *(const float4*)(s_w + n * 4);
                a0 = fmaf(w4.x, v, a0);
                a1 = fmaf(w4.y, v, a1);
                a2 = fmaf(w4.z, v, a2);
                a3 = fmaf(w4.w, v, a3);
            }
            s_part[(0 * 64 + i) * 4 + q4] = a0;
            s_part[(1 * 64 + i) * 4 + q4] = a1;
            s_part[(2 * 64 + i) * 4 + q4] = a2;
            s_part[(3 * 64 + i) * 4 + q4] = a3;
        }
        __syncthreads();
        {
            float4 p = *(const float4*)(s_part + tid * 4);
            s_wv[tid] = (p.x + p.y) + (p.z + p.w);
        }
        __syncthreads();

        // ---- output projection ----
        {
            const float* wvh = s_wv + (h << 6);
            const float4* wv4 = (const float4*)(Wv + tid * DK);
            float a0 = 0.f, a1 = 0.f, a2 = 0.f, a3 = 0.f;
            #pragma unroll
            for (int i = 0; i < 16; i++) {
                float4 w = __ldg(wv4 + i);
                a0 = fmaf(wvh[4 * i + 0], w.x, a0);
                a1 = fmaf(wvh[4 * i + 1], w.y, a1);
                a2 = fmaf(wvh[4 * i + 2], w.z, a2);
                a3 = fmaf(wvh[4 * i + 3], w.w, a3);
            }
            out[(size_t)bt * DOUT + tid] = (a0 + a1) + (a2 + a3);
        }

        buf ^= 1;
    }
}

extern "C" void kernel_launch(void* const* d_in, const int* in_sizes, int n_in,
                              void* d_out, int out_size) {
    (void)n_in; (void)out_size;
    const float* q_x  = (const float*)d_in[0];
    const float* kv_x = (const float*)d_in[1];
    const float* Wk   = (const float*)d_in[2];
    const float* Wq   = (const float*)d_in[3];
    const float* Wv   = (const float*)d_in[4];
    const float* bias = (const float*)d_in[5];
    const float* Ws   = (const float*)d_in[6];
    const float* bs   = (const float*)d_in[7];
    float* out = (float*)d_out;

    const int BT = in_sizes[0] / DK;
    int grid = BT < 152 ? BT : 152;
    // ensure tiles-per-block fits the qb prologue buffer
    while ((BT + grid - 1) / grid > MAXT) grid += 152;
    if (grid > BT) grid = BT;

    cudaFuncSetAttribute(raamh_kernel,
                         cudaFuncAttributeMaxDynamicSharedMemorySize,
                         SMEM_BYTES);
    raamh_kernel<<<grid, TPB, SMEM_BYTES>>>(q_x, kv_x, Wk, Wq, Wv,
                                            bias, Ws, bs, out, BT);
}

// round 9
// speedup vs baseline: 1.1786x; 1.0183x over previous
#include <cuda_runtime.h>
#include <cstdint>
#include <cstddef>

#define TPB   256
#define NKEY  127
#define NH    4
#define DK    64
#define DOUT  256
#define STR   80   // row stride (floats); 80 mod 32 = 16 -> conflict-free LDS.128
#define MAXT  12   // max tiles per block

static constexpr int KV_FLOATS = 128 * STR;
static constexpr int WK_FLOATS = DOUT * STR;
static constexpr int OFF_KV0  = 0;
static constexpr int OFF_KV1  = OFF_KV0 + KV_FLOATS;
static constexpr int OFF_WK   = OFF_KV1 + KV_FLOATS;
static constexpr int OFF_QBA  = OFF_WK + WK_FLOATS;     // [MAXT][256]
static constexpr int OFF_QT   = OFF_QBA + MAXT * DOUT;  // [MAXT][64]
static constexpr int OFF_WS   = OFF_QT + MAXT * DK;
static constexpr int OFF_SC   = OFF_WS + DK;            // [4][128]
static constexpr int OFF_W    = OFF_SC + NH * 128;      // [128][4] n-major
static constexpr int OFF_WV   = OFF_W + 128 * NH;       // [256]
static constexpr int OFF_PART = OFF_WV + DOUT;          // [256][4]
static constexpr int OFF_BS   = OFF_PART + DOUT * 4;
static constexpr int SMEM_FLOATS = OFF_BS + 4;
static constexpr int SMEM_BYTES  = SMEM_FLOATS * 4;

__device__ __forceinline__ float tanh_fast(float x) {
    float y;
    asm("tanh.approx.f32 %0, %1;" : "=f"(y) : "f"(x));
    return y;
}

// m16n8k8 tf32 MMA, row(A) x col(B), fp32 accumulate (arch-neutral PTX)
__device__ __forceinline__ void mma8(float& d0, float& d1, float& d2, float& d3,
                                     float a0, float a1, float a2, float a3,
                                     float b0, float b1) {
    asm volatile(
        "mma.sync.aligned.m16n8k8.row.col.f32.tf32.tf32.f32 "
        "{%0,%1,%2,%3}, {%4,%5,%6,%7}, {%8,%9}, {%0,%1,%2,%3};"
        : "+f"(d0), "+f"(d1), "+f"(d2), "+f"(d3)
        : "r"(__float_as_uint(a0)), "r"(__float_as_uint(a1)),
          "r"(__float_as_uint(a2)), "r"(__float_as_uint(a3)),
          "r"(__float_as_uint(b0)), "r"(__float_as_uint(b1)));
}

#define CP_ASYNC16(sdst, gsrc)                                                \
    asm volatile("cp.async.cg.shared.global [%0], [%1], 16;"                  \
                 :: "r"(sdst), "l"(gsrc))
#define CP_COMMIT() asm volatile("cp.async.commit_group;")
#define CP_WAIT1()  asm volatile("cp.async.wait_group 1;")

__device__ __forceinline__ void prefetch_kv(const float* __restrict__ gsrc,
                                            float* sdst) {
    #pragma unroll 2
    for (int j = threadIdx.x; j < NKEY * 16; j += TPB) {
        int row = j >> 4;
        int c4  = j & 15;
        unsigned sa =
            (unsigned)__cvta_generic_to_shared(sdst + row * STR + c4 * 4);
        CP_ASYNC16(sa, gsrc + j * 4);
    }
}

__global__ void __launch_bounds__(TPB, 1)
raamh_kernel(const float* __restrict__ q_x, const float* __restrict__ kv_x,
             const float* __restrict__ Wk,  const float* __restrict__ Wq,
             const float* __restrict__ Wv,  const float* __restrict__ bias,
             const float* __restrict__ Ws,  const float* __restrict__ bs,
             float* __restrict__ out, int BT)
{
    extern __shared__ float smem[];
    float* s_kv[2] = { smem + OFF_KV0, smem + OFF_KV1 };
    float* s_wk   = smem + OFF_WK;
    float* s_qba  = smem + OFF_QBA;
    float* s_qt   = smem + OFF_QT;
    float* s_ws   = smem + OFF_WS;
    float* s_sc   = smem + OFF_SC;
    float* s_w    = smem + OFF_W;     // [n][4] heads, n-major
    float* s_wv   = smem + OFF_WV;
    float* s_part = smem + OFF_PART;
    float* s_bs   = smem + OFF_BS;

    const int tid  = threadIdx.x;
    const int lane = tid & 31;
    const int wrp  = tid >> 5;
    const int g    = lane >> 2;       // fragment row group
    const int tg   = lane & 3;        // fragment col group
    const int h    = tid >> 6;
    // one warp-task: head = wrp&3 (64 o), nh = wrp>>2 (64 n)
    const int headw = wrp & 3;
    const int nh    = wrp >> 2;

    const int bt0  = blockIdx.x;
    const int grid = gridDim.x;
    int ntiles = (BT - bt0 + grid - 1) / grid;
    if (ntiles > MAXT) ntiles = MAXT;

    // ---- one-time staging: Wk (stride 80) + q vectors for all tiles ----
    {
        const float4* wk4 = (const float4*)Wk;
        #pragma unroll 4
        for (int j = tid; j < DOUT * 16; j += TPB) {
            int row = j >> 4, c4 = j & 15;
            float4 v = wk4[j];
            *(float4*)(s_wk + row * STR + c4 * 4) = v;
        }
        if (tid < DK) s_ws[tid] = Ws[tid];
        if (tid == 0) s_bs[0] = bs[0];
        if (tid < 128)   // zero garbage row 127 of both kv buffers
            s_kv[tid >> 6][127 * STR + (tid & 63)] = 0.f;
        for (int idx = tid; idx < ntiles * DK; idx += TPB) {
            int t = idx >> 6, k = idx & 63;
            s_qt[t * DK + k] = q_x[(size_t)(bt0 + t * grid) * DK + k];
        }
    }
    __syncthreads();

    // ---- prologue: qb for every tile (thread owns output o = tid) ----
    {
        float4 wq[16];
        const float4* wq4 = (const float4*)(Wq + tid * DK);
        #pragma unroll
        for (int i = 0; i < 16; i++) wq[i] = __ldg(wq4 + i);
        const float bb = __ldg(bias + (tid & (DK - 1)));
        for (int t = 0; t < ntiles; ++t) {
            const float* qq = s_qt + t * DK;
            float a0 = 0.f, a1 = 0.f, a2 = 0.f, a3 = 0.f;
            #pragma unroll
            for (int i = 0; i < 16; i++) {
                a0 = fmaf(qq[4 * i + 0], wq[i].x, a0);
                a1 = fmaf(qq[4 * i + 1], wq[i].y, a1);
                a2 = fmaf(qq[4 * i + 2], wq[i].z, a2);
                a3 = fmaf(qq[4 * i + 3], wq[i].w, a3);
            }
            s_qba[t * DOUT + tid] = (a0 + a1) + (a2 + a3) + bb;
        }
    }

    int buf = 0;
    prefetch_kv(kv_x + (size_t)bt0 * (NKEY * DK), s_kv[0]);
    CP_COMMIT();

    int ti = 0;
    for (int bt = bt0; bt < BT; bt += grid, ++ti) {
        int bt_next = bt + grid;
        if (bt_next < BT)
            prefetch_kv(kv_x + (size_t)bt_next * (NKEY * DK), s_kv[buf ^ 1]);
        CP_COMMIT();
        CP_WAIT1();
        __syncthreads();

        const float* kvb = s_kv[buf];
        const float* qbt = s_qba + ti * DOUT;
        const float  bsv = s_bs[0];

        // ---- score GEMM via tf32 mma.sync; one 64n x 64o task per warp ----
        {
            const float* kvp = kvb + (nh * 64) * STR;
            const float* wkp = s_wk + (headw * 64) * STR;

            float acc[4][8][4];
            #pragma unroll
            for (int mb = 0; mb < 4; ++mb)
                #pragma unroll
                for (int nb = 0; nb < 8; ++nb)
                    #pragma unroll
                    for (int c = 0; c < 4; ++c) acc[mb][nb][c] = 0.f;

            #pragma unroll
            for (int ks = 0; ks < 4; ++ks) {
                const int kc = ks * 16 + tg * 4;
                float4 av[4][2];
                #pragma unroll
                for (int mb = 0; mb < 4; ++mb) {
                    const float* ar = kvp + (mb * 16 + g) * STR + kc;
                    av[mb][0] = *(const float4*)ar;
                    av[mb][1] = *(const float4*)(ar + 8 * STR);
                }
                #pragma unroll
                for (int nb = 0; nb < 8; ++nb) {
                    float4 bv =
                        *(const float4*)(wkp + (nb * 8 + g) * STR + kc);
                    #pragma unroll
                    for (int mb = 0; mb < 4; ++mb) {
                        mma8(acc[mb][nb][0], acc[mb][nb][1],
                             acc[mb][nb][2], acc[mb][nb][3],
                             av[mb][0].x, av[mb][1].x,
                             av[mb][0].y, av[mb][1].y,
                             bv.x, bv.y);
                        mma8(acc[mb][nb][0], acc[mb][nb][1],
                             acc[mb][nb][2], acc[mb][nb][3],
                             av[mb][0].z, av[mb][1].z,
                             av[mb][0].w, av[mb][1].w,
                             bv.z, bv.w);
                    }
                }
            }

            // epilogue: tanh + Ws reduction over this head's 64 o
            float part[4][2];
            #pragma unroll
            for (int mb = 0; mb < 4; ++mb) {
                part[mb][0] = 0.f;
                part[mb][1] = 0.f;
            }
            #pragma unroll
            for (int nb = 0; nb < 8; ++nb) {
                #pragma unroll
                for (int cc = 0; cc < 2; ++cc) {
                    const int k = nb * 8 + tg * 2 + cc;
                    const float wsk = s_ws[k];
                    const float qbo = qbt[headw * 64 + k];
                    #pragma unroll
                    for (int mb = 0; mb < 4; ++mb) {
                        part[mb][0] = fmaf(
                            wsk, tanh_fast(acc[mb][nb][cc] + qbo),
                            part[mb][0]);
                        part[mb][1] = fmaf(
                            wsk, tanh_fast(acc[mb][nb][2 + cc] + qbo),
                            part[mb][1]);
                    }
                }
            }
            #pragma unroll
            for (int m = 1; m <= 2; m <<= 1) {
                #pragma unroll
                for (int mb = 0; mb < 4; ++mb) {
                    part[mb][0] += __shfl_xor_sync(0xffffffffu, part[mb][0], m);
                    part[mb][1] += __shfl_xor_sync(0xffffffffu, part[mb][1], m);
                }
            }
            if (tg == 0) {
                #pragma unroll
                for (int mb = 0; mb < 4; ++mb) {
                    const int r = nh * 64 + mb * 16 + g;
                    s_sc[headw * 128 + r]     = part[mb][0] + bsv;
                    s_sc[headw * 128 + r + 8] = part[mb][1] + bsv;
                }
            }
        }
        __syncthreads();

        // ---- softmax per head (one warp per head), n-major s_w ----
        if (tid < NH * 32) {
            int hh = tid >> 5;
            int ln = tid & 31;
            const float* sc = s_sc + hh * 128;
            float v0 = sc[ln];
            float v1 = sc[ln + 32];
            float v2 = sc[ln + 64];
            float v3 = (ln + 96 < NKEY) ? sc[ln + 96] : -1e30f;
            float m = fmaxf(fmaxf(v0, v1), fmaxf(v2, v3));
            #pragma unroll
            for (int o = 16; o > 0; o >>= 1)
                m = fmaxf(m, __shfl_xor_sync(0xffffffffu, m, o));
            float e0 = __expf(v0 - m);
            float e1 = __expf(v1 - m);
            float e2 = __expf(v2 - m);
            float e3 = (ln + 96 < NKEY) ? __expf(v3 - m) : 0.f;
            float s = (e0 + e1) + (e2 + e3);
            #pragma unroll
            for (int o = 16; o > 0; o >>= 1)
                s += __shfl_xor_sync(0xffffffffu, s, o);
            float inv = 1.f / s;
            s_w[ln * 4 + hh]        = e0 * inv;
            s_w[(ln + 32) * 4 + hh] = e1 * inv;
            s_w[(ln + 64) * 4 + hh] = e2 * inv;
            if (ln + 96 < NKEY) s_w[(ln + 96) * 4 + hh] = e3 * inv;
        }
        __syncthreads();

        // ---- weighted kv sum, quarter-split over n ----
        {
            const int q4 = tid >> 6;
            const int i  = tid & 63;
            float a0 = 0.f, a1 = 0.f, a2 = 0.f, a3 = 0.f;
            const int n0 = q4 * 32;
            const int n1 = (q4 == 3) ? NKEY : n0 + 32;
            #pragma unroll 4
            for (int n = n0; n < n1; ++n) {
                float  v  = kvb[n * STR + i];
                float4 w4 = *(const float4*)(s_w + n * 4);
                a0 = fmaf(w4.x, v, a0);
                a1 = fmaf(w4.y, v, a1);
                a2 = fmaf(w4.z, v, a2);
                a3 = fmaf(w4.w, v, a3);
            }
            s_part[(0 * 64 + i) * 4 + q4] = a0;
            s_part[(1 * 64 + i) * 4 + q4] = a1;
            s_part[(2 * 64 + i) * 4 + q4] = a2;
            s_part[(3 * 64 + i) * 4 + q4] = a3;
        }
        __syncthreads();
        {
            float4 p = *(const float4*)(s_part + tid * 4);
            s_wv[tid] = (p.x + p.y) + (p.z + p.w);
        }
        __syncthreads();

        // ---- output projection ----
        {
            const float* wvh = s_wv + (h << 6);
            const float4* wv4 = (const float4*)(Wv + tid * DK);
            float a0 = 0.f, a1 = 0.f, a2 = 0.f, a3 = 0.f;
            #pragma unroll
            for (int i = 0; i < 16; i++) {
                float4 w = __ldg(wv4 + i);
                a0 = fmaf(wvh[4 * i + 0], w.x, a0);
                a1 = fmaf(wvh[4 * i + 1], w.y, a1);
                a2 = fmaf(wvh[4 * i + 2], w.z, a2);
                a3 = fmaf(wvh[4 * i + 3], w.w, a3);
            }
            out[(size_t)bt * DOUT + tid] = (a0 + a1) + (a2 + a3);
        }

        buf ^= 1;
    }
}

extern "C" void kernel_launch(void* const* d_in, const int* in_sizes, int n_in,
                              void* d_out, int out_size) {
    (void)n_in; (void)out_size;
    const float* q_x  = (const float*)d_in[0];
    const float* kv_x = (const float*)d_in[1];
    const float* Wk   = (const float*)d_in[2];
    const float* Wq   = (const float*)d_in[3];
    const float* Wv   = (const float*)d_in[4];
    const float* bias = (const float*)d_in[5];
    const float* Ws   = (const float*)d_in[6];
    const float* bs   = (const float*)d_in[7];
    float* out = (float*)d_out;

    const int BT = in_sizes[0] / DK;
    int grid = BT < 152 ? BT : 152;
    while ((BT + grid - 1) / grid > MAXT) grid += 152;
    if (grid > BT) grid = BT;

    cudaFuncSetAttribute(raamh_kernel,
                         cudaFuncAttributeMaxDynamicSharedMemorySize,
                         SMEM_BYTES);
    raamh_kernel<<<grid, TPB, SMEM_BYTES>>>(q_x, kv_x, Wk, Wq, Wv,
                                            bias, Ws, bs, out, BT);
}

// round 10
// speedup vs baseline: 1.3480x; 1.1437x over previous
#include <cuda_runtime.h>
#include <cuda_fp16.h>
#include <cstdint>
#include <cstddef>

#define TPB   128
#define NKEY  127
#define NH    4
#define DK    64
#define DOUT  256
#define STRH  80    // fp16 row stride in halves (160B); 40 words = 8 mod 32
#define STGF  68    // fp32 staging row stride in floats (272B, 16B-multiple)
#define MAXT  4

static constexpr int OFFB_STG  = 0;
static constexpr int OFFB_KV16 = OFFB_STG  + 128 * STGF * 4;   // 34816
static constexpr int OFFB_WK16 = OFFB_KV16 + 128 * STRH * 2;   // +20480
static constexpr int OFFB_QBA  = OFFB_WK16 + 256 * STRH * 2;   // +40960
static constexpr int OFFB_QT   = OFFB_QBA + MAXT * DOUT * 4;
static constexpr int OFFB_WS   = OFFB_QT + MAXT * DK * 4;
static constexpr int OFFB_SC   = OFFB_WS + DK * 4;             // [4][128]
static constexpr int OFFB_W    = OFFB_SC + NH * 128 * 4;       // [128][4]
static constexpr int OFFB_WV   = OFFB_W + 128 * NH * 4;        // [256]
static constexpr int OFFB_PART = OFFB_WV + DOUT * 4;           // [256][5]
static constexpr int OFFB_BS   = OFFB_PART + DOUT * 5 * 4;
static constexpr int SMEM_BYTES = OFFB_BS + 16;                // ~111.9KB

__device__ __forceinline__ float tanh_fast(float x) {
    float y;
    asm("tanh.approx.f32 %0, %1;" : "=f"(y) : "f"(x));
    return y;
}
__device__ __forceinline__ uint32_t f2h2(float a, float b) {
    __half2 h = __floats2half2_rn(a, b);
    return *(uint32_t*)&h;
}

// m16n8k16 fp16 MMA, row(A) x col(B), fp32 accumulate (arch-neutral PTX)
__device__ __forceinline__ void mma16(float& d0, float& d1, float& d2,
                                      float& d3, uint32_t a0, uint32_t a1,
                                      uint32_t a2, uint32_t a3,
                                      uint32_t b0, uint32_t b1) {
    asm volatile(
        "mma.sync.aligned.m16n8k16.row.col.f32.f16.f16.f32 "
        "{%0,%1,%2,%3}, {%4,%5,%6,%7}, {%8,%9}, {%0,%1,%2,%3};"
        : "+f"(d0), "+f"(d1), "+f"(d2), "+f"(d3)
        : "r"(a0), "r"(a1), "r"(a2), "r"(a3), "r"(b0), "r"(b1));
}

#define CP_ASYNC16(sdst, gsrc)                                                \
    asm volatile("cp.async.cg.shared.global [%0], [%1], 16;"                  \
                 :: "r"(sdst), "l"(gsrc))
#define CP_COMMIT() asm volatile("cp.async.commit_group;")
#define CP_WAIT0()  asm volatile("cp.async.wait_group 0;")

__device__ __forceinline__ void prefetch_kv(const float* __restrict__ gsrc,
                                            float* stg) {
    #pragma unroll 1
    for (int j = threadIdx.x; j < NKEY * 16; j += TPB) {
        int row = j >> 4;
        int c4  = j & 15;
        unsigned sa =
            (unsigned)__cvta_generic_to_shared(stg + row * STGF + c4 * 4);
        CP_ASYNC16(sa, gsrc + j * 4);
    }
}

__global__ void __launch_bounds__(TPB, 2)
raamh_kernel(const float* __restrict__ q_x, const float* __restrict__ kv_x,
             const float* __restrict__ Wk,  const float* __restrict__ Wq,
             const float* __restrict__ Wv,  const float* __restrict__ bias,
             const float* __restrict__ Ws,  const float* __restrict__ bs,
             float* __restrict__ out, int BT)
{
    extern __shared__ char smem[];
    float*  s_stg  = (float*) (smem + OFFB_STG);
    __half* s_kvh  = (__half*)(smem + OFFB_KV16);
    __half* s_wkh  = (__half*)(smem + OFFB_WK16);
    float*  s_qba  = (float*) (smem + OFFB_QBA);
    float*  s_qt   = (float*) (smem + OFFB_QT);
    float*  s_ws   = (float*) (smem + OFFB_WS);
    float*  s_sc   = (float*) (smem + OFFB_SC);
    float*  s_w    = (float*) (smem + OFFB_W);
    float*  s_wv   = (float*) (smem + OFFB_WV);
    float*  s_part = (float*) (smem + OFFB_PART);
    float*  s_bs   = (float*) (smem + OFFB_BS);

    const int tid  = threadIdx.x;
    const int lane = tid & 31;
    const int wrp  = tid >> 5;       // 0..3; warp's head = wrp
    const int g    = lane >> 2;
    const int tg   = lane & 3;

    const int bt0  = blockIdx.x;
    const int grid = gridDim.x;
    int ntiles = (BT - bt0 + grid - 1) / grid;
    if (ntiles > MAXT) ntiles = MAXT;
    if (ntiles < 1) return;

    // issue first kv prefetch immediately (overlap with init)
    prefetch_kv(kv_x + (size_t)bt0 * (NKEY * DK), s_stg);
    CP_COMMIT();

    // ---- one-time staging: Wk -> fp16 (stride 80 halves), ws, bs, qt ----
    {
        #pragma unroll 1
        for (int j = tid; j < DOUT * 16; j += TPB) {
            int row = j >> 4, c4 = (j & 15) * 4;
            float4 v = __ldg((const float4*)(Wk + row * DK + c4));
            uint2 hh = make_uint2(f2h2(v.x, v.y), f2h2(v.z, v.w));
            *(uint2*)(s_wkh + row * STRH + c4) = hh;
        }
        if (tid < DK) s_ws[tid] = Ws[tid];
        if (tid == 0) s_bs[0] = bs[0];
        for (int idx = tid; idx < ntiles * DK; idx += TPB) {
            int t = idx >> 6, k = idx & 63;
            s_qt[t * DK + k] = q_x[(size_t)(bt0 + t * grid) * DK + k];
        }
    }
    __syncthreads();

    // ---- prologue: qb for every tile; thread covers o = tid, tid+128 ----
    #pragma unroll 1
    for (int rep = 0; rep < 2; ++rep) {
        const int o = tid + rep * 128;
        float4 wq[16];
        const float4* wq4 = (const float4*)(Wq + o * DK);
        #pragma unroll
        for (int i = 0; i < 16; i++) wq[i] = __ldg(wq4 + i);
        const float bb = __ldg(bias + (o & (DK - 1)));
        #pragma unroll 1
        for (int t = 0; t < ntiles; ++t) {
            const float* qq = s_qt + t * DK;
            float a0 = 0.f, a1 = 0.f, a2 = 0.f, a3 = 0.f;
            #pragma unroll
            for (int i = 0; i < 16; i++) {
                a0 = fmaf(qq[4 * i + 0], wq[i].x, a0);
                a1 = fmaf(qq[4 * i + 1], wq[i].y, a1);
                a2 = fmaf(qq[4 * i + 2], wq[i].z, a2);
                a3 = fmaf(qq[4 * i + 3], wq[i].w, a3);
            }
            s_qba[t * DOUT + o] = (a0 + a1) + (a2 + a3) + bb;
        }
    }

    int ti = 0;
    for (int bt = bt0; bt < BT; bt += grid, ++ti) {
        // staging now holds tile ti's fp32 kv
        CP_WAIT0();
        __syncthreads();

        // ---- convert staging -> fp16 kv (thread t = row t) ----
        if (tid < NKEY) {
            const float* src = s_stg + tid * STGF;
            __half* dst = s_kvh + tid * STRH;
            #pragma unroll
            for (int u = 0; u < 16; ++u) {
                float4 v = *(const float4*)(src + u * 4);
                uint2 hh = make_uint2(f2h2(v.x, v.y), f2h2(v.z, v.w));
                *(uint2*)(dst + u * 4) = hh;
            }
        } else {  // zero row 127
            uint2 z = make_uint2(0u, 0u);
            __half* dst = s_kvh + 127 * STRH;
            #pragma unroll
            for (int u = 0; u < 16; ++u) *(uint2*)(dst + u * 4) = z;
        }
        __syncthreads();   // conversion done; staging free for next prefetch

        int bt_next = bt + grid;
        if (bt_next < BT)
            prefetch_kv(kv_x + (size_t)bt_next * (NKEY * DK), s_stg);
        CP_COMMIT();

        const float* qbt = s_qba + ti * DOUT;
        const float  bsv = s_bs[0];
        const int head = wrp;

        // ---- score GEMM: fp16 m16n8k16; warp = head, 2 nh tasks ----
        #pragma unroll 1
        for (int nh = 0; nh < 2; ++nh) {
            const __half* kvp = s_kvh + (nh * 64) * STRH;
            const __half* wkp = s_wkh + (head * 64) * STRH;

            float acc[4][8][4];
            #pragma unroll
            for (int mb = 0; mb < 4; ++mb)
                #pragma unroll
                for (int nb = 0; nb < 8; ++nb)
                    #pragma unroll
                    for (int c = 0; c < 4; ++c) acc[mb][nb][c] = 0.f;

            #pragma unroll
            for (int kc = 0; kc < 4; ++kc) {
                const int ho = kc * 16 + 4 * tg;   // permuted k slots
                uint2 u[4], v[4];
                #pragma unroll
                for (int mb = 0; mb < 4; ++mb) {
                    const __half* ar = kvp + (mb * 16 + g) * STRH + ho;
                    u[mb] = *(const uint2*)ar;
                    v[mb] = *(const uint2*)(ar + 8 * STRH);
                }
                #pragma unroll
                for (int nb = 0; nb < 8; ++nb) {
                    uint2 w = *(const uint2*)(wkp + (nb * 8 + g) * STRH + ho);
                    #pragma unroll
                    for (int mb = 0; mb < 4; ++mb)
                        mma16(acc[mb][nb][0], acc[mb][nb][1],
                              acc[mb][nb][2], acc[mb][nb][3],
                              u[mb].x, v[mb].x, u[mb].y, v[mb].y,
                              w.x, w.y);
                }
            }

            // epilogue: tanh + Ws reduction over this head's 64 o
            float part[4][2];
            #pragma unroll
            for (int mb = 0; mb < 4; ++mb) {
                part[mb][0] = 0.f;
                part[mb][1] = 0.f;
            }
            #pragma unroll
            for (int nb = 0; nb < 8; ++nb) {
                #pragma unroll
                for (int cc = 0; cc < 2; ++cc) {
                    const int k = nb * 8 + tg * 2 + cc;
                    const float wsk = s_ws[k];
                    const float qbo = qbt[head * 64 + k];
                    #pragma unroll
                    for (int mb = 0; mb < 4; ++mb) {
                        part[mb][0] = fmaf(
                            wsk, tanh_fast(acc[mb][nb][cc] + qbo),
                            part[mb][0]);
                        part[mb][1] = fmaf(
                            wsk, tanh_fast(acc[mb][nb][2 + cc] + qbo),
                            part[mb][1]);
                    }
                }
            }
            #pragma unroll
            for (int m = 1; m <= 2; m <<= 1) {
                #pragma unroll
                for (int mb = 0; mb < 4; ++mb) {
                    part[mb][0] += __shfl_xor_sync(0xffffffffu, part[mb][0], m);
                    part[mb][1] += __shfl_xor_sync(0xffffffffu, part[mb][1], m);
                }
            }
            if (tg == 0) {
                #pragma unroll
                for (int mb = 0; mb < 4; ++mb) {
                    const int r = nh * 64 + mb * 16 + g;
                    s_sc[head * 128 + r]     = part[mb][0] + bsv;
                    s_sc[head * 128 + r + 8] = part[mb][1] + bsv;
                }
            }
        }
        __syncthreads();

        // ---- softmax per head (warp per head), n-major s_w ----
        {
            int hh = wrp;
            int ln = lane;
            const float* sc = s_sc + hh * 128;
            float v0 = sc[ln];
            float v1 = sc[ln + 32];
            float v2 = sc[ln + 64];
            float v3 = (ln + 96 < NKEY) ? sc[ln + 96] : -1e30f;
            float m = fmaxf(fmaxf(v0, v1), fmaxf(v2, v3));
            #pragma unroll
            for (int o = 16; o > 0; o >>= 1)
                m = fmaxf(m, __shfl_xor_sync(0xffffffffu, m, o));
            float e0 = __expf(v0 - m);
            float e1 = __expf(v1 - m);
            float e2 = __expf(v2 - m);
            float e3 = (ln + 96 < NKEY) ? __expf(v3 - m) : 0.f;
            float s = (e0 + e1) + (e2 + e3);
            #pragma unroll
            for (int o = 16; o > 0; o >>= 1)
                s += __shfl_xor_sync(0xffffffffu, s, o);
            float inv = 1.f / s;
            s_w[ln * 4 + hh]        = e0 * inv;
            s_w[(ln + 32) * 4 + hh] = e1 * inv;
            s_w[(ln + 64) * 4 + hh] = e2 * inv;
            if (ln + 96 < NKEY) s_w[(ln + 96) * 4 + hh] = e3 * inv;
        }
        __syncthreads();

        // ---- weighted kv sum: thread = (col pair, n-group) ----
        {
            const int cp = tid & 31;          // cols 2cp, 2cp+1
            const int ng = tid >> 5;          // 4 n-groups of 32
            const int n0 = ng * 32;
            const int n1 = (ng == 3) ? NKEY : n0 + 32;
            float ax[4] = {0.f, 0.f, 0.f, 0.f};
            float ay[4] = {0.f, 0.f, 0.f, 0.f};
            #pragma unroll 4
            for (int n = n0; n < n1; ++n) {
                __half2 h2 = *(const __half2*)(s_kvh + n * STRH + 2 * cp);
                float2 f = __half22float2(h2);
                float4 w4 = *(const float4*)(s_w + n * 4);
                ax[0] = fmaf(w4.x, f.x, ax[0]);
                ax[1] = fmaf(w4.y, f.x, ax[1]);
                ax[2] = fmaf(w4.z, f.x, ax[2]);
                ax[3] = fmaf(w4.w, f.x, ax[3]);
                ay[0] = fmaf(w4.x, f.y, ay[0]);
                ay[1] = fmaf(w4.y, f.y, ay[1]);
                ay[2] = fmaf(w4.z, f.y, ay[2]);
                ay[3] = fmaf(w4.w, f.y, ay[3]);
            }
            #pragma unroll
            for (int hh = 0; hh < 4; ++hh) {
                s_part[(hh * 64 + 2 * cp) * 5 + ng]     = ax[hh];
                s_part[(hh * 64 + 2 * cp + 1) * 5 + ng] = ay[hh];
            }
        }
        __syncthreads();
        #pragma unroll
        for (int rep = 0; rep < 2; ++rep) {
            const int o = tid + rep * 128;
            const float* p = s_part + o * 5;
            s_wv[o] = (p[0] + p[1]) + (p[2] + p[3]);
        }
        __syncthreads();

        // ---- output projection: thread covers o = tid, tid+128 ----
        #pragma unroll 1
        for (int rep = 0; rep < 2; ++rep) {
            const int o = tid + rep * 128;
            const float* wvh = s_wv + (o >> 6) * 64;
            const float4* wv4 = (const float4*)(Wv + o * DK);
            float a0 = 0.f, a1 = 0.f, a2 = 0.f, a3 = 0.f;
            #pragma unroll
            for (int i = 0; i < 16; i++) {
                float4 w = __ldg(wv4 + i);
                a0 = fmaf(wvh[4 * i + 0], w.x, a0);
                a1 = fmaf(wvh[4 * i + 1], w.y, a1);
                a2 = fmaf(wvh[4 * i + 2], w.z, a2);
                a3 = fmaf(wvh[4 * i + 3], w.w, a3);
            }
            out[(size_t)bt * DOUT + o] = (a0 + a1) + (a2 + a3);
        }
    }
}

extern "C" void kernel_launch(void* const* d_in, const int* in_sizes, int n_in,
                              void* d_out, int out_size) {
    (void)n_in; (void)out_size;
    const float* q_x  = (const float*)d_in[0];
    const float* kv_x = (const float*)d_in[1];
    const float* Wk   = (const float*)d_in[2];
    const float* Wq   = (const float*)d_in[3];
    const float* Wv   = (const float*)d_in[4];
    const float* bias = (const float*)d_in[5];
    const float* Ws   = (const float*)d_in[6];
    const float* bs   = (const float*)d_in[7];
    float* out = (float*)d_out;

    const int BT = in_sizes[0] / DK;
    int grid = 2 * 152;                       // 2 blocks per SM
    if (grid > BT) grid = BT;
    while ((BT + grid - 1) / grid > MAXT) grid += 2 * 152;

    cudaFuncSetAttribute(raamh_kernel,
                         cudaFuncAttributeMaxDynamicSharedMemorySize,
                         SMEM_BYTES);
    raamh_kernel<<<grid, TPB, SMEM_BYTES>>>(q_x, kv_x, Wk, Wq, Wv,
                                            bias, Ws, bs, out, BT);
}